// round 1
// baseline (speedup 1.0000x reference)
#include <cuda_runtime.h>
#include <cuda_bf16.h>
#include <math.h>

// ---------------- problem constants ----------------
#define B_   1024
#define M_   16384
#define D_   512
#define C_   100
#define L_   50
#define INV_TEMP 5.0f   // 1/0.2
#define RATIO 0.7f

// ---------------- device scratch (no allocations allowed) ----------------
__device__ float g_fnorm[B_ * D_];          // normalized features   (2 MB)
__device__ float g_bnorm[M_ * D_];          // normalized buffer     (32 MB)
__device__ float g_sims[(size_t)B_ * M_];   // similarity matrix     (64 MB)
__device__ float g_opn[L_ * D_];            // normalized old protos (gathered)
__device__ float g_npn[L_ * D_];            // normalized new protos (gathered)
__device__ float g_cnt[C_];                 // class counts
__device__ float g_sumS[C_];                // class score sums
__device__ float g_sumF[C_ * D_];           // class feature sums
__device__ float g_sumSq[C_ * D_];          // class feature^2 sums
__device__ float g_rowloss[B_];
__device__ int   g_rowvalid[B_];
__device__ float g_kl[1];

// ---------------- K0: zero accumulators ----------------
__global__ void zero_kernel() {
    int i = blockIdx.x * blockDim.x + threadIdx.x;
    if (i < C_ * D_) { g_sumF[i] = 0.f; g_sumSq[i] = 0.f; }
    if (i < C_)      { g_cnt[i] = 0.f; g_sumS[i] = 0.f; }
    if (i == 0)      { g_kl[0] = 0.f; }
}

// ---------------- K1: normalize rows (+ boundary stats for feature rows) ----
// blocks: [0,1024) features, [1024,17408) buffer, [17408,17458) old protos,
//         [17458,17508) new protos.  128 threads, 4 floats/thread.
__global__ void __launch_bounds__(128) normalize_kernel(
    const float* __restrict__ features, const float* __restrict__ buffer,
    const float* __restrict__ oldp, const float* __restrict__ newp,
    const float* __restrict__ W, const float* __restrict__ bbias,
    const int* __restrict__ labels, const int* __restrict__ lc)
{
    const int blk = blockIdx.x;
    const int tid = threadIdx.x;
    const float* src; float* dst; bool isFeat = false;
    if (blk < B_) { src = features + blk * D_; dst = g_fnorm + blk * D_; isFeat = true; }
    else if (blk < B_ + M_) { int r = blk - B_; src = buffer + (size_t)r * D_; dst = g_bnorm + (size_t)r * D_; }
    else if (blk < B_ + M_ + L_) { int j = blk - (B_ + M_); src = oldp + lc[j] * D_; dst = g_opn + j * D_; }
    else { int j = blk - (B_ + M_ + L_); src = newp + lc[j] * D_; dst = g_npn + j * D_; }

    float4 v = *(const float4*)(src + tid * 4);
    float ss = v.x*v.x + v.y*v.y + v.z*v.z + v.w*v.w;
    float wd = 0.f;
    if (isFeat) {
        float4 w4 = *(const float4*)(W + tid * 4);
        wd = v.x*w4.x + v.y*w4.y + v.z*w4.z + v.w*w4.w;
    }
    __shared__ float sh1[128], sh2[128];
    sh1[tid] = ss; sh2[tid] = wd; __syncthreads();
    #pragma unroll
    for (int off = 64; off > 0; off >>= 1) {
        if (tid < off) { sh1[tid] += sh1[tid + off]; sh2[tid] += sh2[tid + off]; }
        __syncthreads();
    }
    float inv = 1.0f / fmaxf(sqrtf(sh1[0]), 1e-12f);
    float4 o; o.x = v.x*inv; o.y = v.y*inv; o.z = v.z*inv; o.w = v.w*inv;
    *(float4*)(dst + tid * 4) = o;

    if (isFeat) {
        int cl = labels[blk];
        if (tid == 0) {
            float score = 1.0f / (1.0f + __expf(-(sh2[0] + bbias[0])));
            atomicAdd(&g_cnt[cl], 1.0f);
            atomicAdd(&g_sumS[cl], score);
        }
        int base = cl * D_ + tid * 4;
        atomicAdd(&g_sumF[base + 0], v.x); atomicAdd(&g_sumSq[base + 0], v.x*v.x);
        atomicAdd(&g_sumF[base + 1], v.y); atomicAdd(&g_sumSq[base + 1], v.y*v.y);
        atomicAdd(&g_sumF[base + 2], v.z); atomicAdd(&g_sumSq[base + 2], v.z*v.z);
        atomicAdd(&g_sumF[base + 3], v.w); atomicAdd(&g_sumSq[base + 3], v.w*v.w);
    }
}

// ---------------- K2: SGEMM sims = fnorm @ bnorm^T * 5, clipped -------------
// 128x128 tile, BK=32, 256 threads, 8x8 per thread.
__global__ void __launch_bounds__(256) gemm_sims_kernel() {
    __shared__ float As[32][129];
    __shared__ float Bs[32][129];
    const int tid = threadIdx.x;
    const int tx = tid & 15;    // N dir
    const int ty = tid >> 4;    // M dir
    const int rowBase = blockIdx.y * 128;
    const int colBase = blockIdx.x * 128;
    const int lrg = tid >> 3;          // 0..31
    const int lk  = (tid & 7) * 4;     // 0..28

    float acc[8][8];
    #pragma unroll
    for (int i = 0; i < 8; i++)
        #pragma unroll
        for (int j = 0; j < 8; j++) acc[i][j] = 0.f;

    for (int k0 = 0; k0 < D_; k0 += 32) {
        #pragma unroll
        for (int i = 0; i < 4; i++) {
            int r = lrg + i * 32;
            float4 va = *(const float4*)&g_fnorm[(rowBase + r) * D_ + k0 + lk];
            As[lk+0][r] = va.x; As[lk+1][r] = va.y; As[lk+2][r] = va.z; As[lk+3][r] = va.w;
            float4 vb = *(const float4*)&g_bnorm[(colBase + r) * D_ + k0 + lk];
            Bs[lk+0][r] = vb.x; Bs[lk+1][r] = vb.y; Bs[lk+2][r] = vb.z; Bs[lk+3][r] = vb.w;
        }
        __syncthreads();
        #pragma unroll
        for (int k = 0; k < 32; k++) {
            float a[8], b[8];
            #pragma unroll
            for (int i = 0; i < 8; i++) a[i] = As[k][ty*8 + i];
            #pragma unroll
            for (int j = 0; j < 8; j++) b[j] = Bs[k][tx*8 + j];
            #pragma unroll
            for (int i = 0; i < 8; i++)
                #pragma unroll
                for (int j = 0; j < 8; j++) acc[i][j] = fmaf(a[i], b[j], acc[i][j]);
        }
        __syncthreads();
    }
    #pragma unroll
    for (int i = 0; i < 8; i++) {
        int r = rowBase + ty*8 + i;
        size_t base = (size_t)r * M_ + colBase + tx*8;
        #pragma unroll
        for (int j = 0; j < 8; j++) {
            float s = fminf(fmaxf(acc[i][j] * INV_TEMP, -10.f), 10.f);
            g_sims[base + j] = s;
        }
    }
}

// ---------------- K3: per-row hard-negative loss ---------------------------
// One block (256 threads) per row. Warp-private 512-bin histograms
// (count + expsum), reduce, then top-k selection by descending bin scan.
#define NB 512
#define HSCALE 25.6f   // NB / 20
__global__ void __launch_bounds__(256) hard_kernel(
    const int* __restrict__ labels, const int* __restrict__ blabels)
{
    const int r   = blockIdx.x;
    const int tid = threadIdx.x;
    const int wid = tid >> 5;
    __shared__ int   hcnt[8][NB];
    __shared__ float hsum[8][NB];
    __shared__ float s_pos; __shared__ int s_npos, s_nneg;

    for (int i = tid; i < 8 * NB; i += 256) { ((int*)hcnt)[i] = 0; ((float*)hsum)[i] = 0.f; }
    if (tid == 0) { s_pos = 0.f; s_npos = 0; s_nneg = 0; }
    __syncthreads();

    const int lbl = labels[r];
    const float* __restrict__ row = g_sims + (size_t)r * M_;
    float lpos = 0.f; int lnp = 0, lnn = 0;
    for (int m = tid; m < M_; m += 256) {
        float s = row[m];
        float e = __expf(s);
        if (blabels[m] != lbl) {
            lnn++;
            int bin = (int)((s + 10.f) * HSCALE);
            bin = min(max(bin, 0), NB - 1);
            atomicAdd(&hcnt[wid][bin], 1);
            atomicAdd(&hsum[wid][bin], e);
        } else { lpos += e; lnp++; }
    }
    atomicAdd(&s_pos, lpos); atomicAdd(&s_npos, lnp); atomicAdd(&s_nneg, lnn);
    __syncthreads();

    // reduce 8 warp copies into copy 0
    for (int b = tid; b < NB; b += 256) {
        int c = hcnt[0][b]; float s = hsum[0][b];
        #pragma unroll
        for (int w = 1; w < 8; w++) { c += hcnt[w][b]; s += hsum[w][b]; }
        hcnt[0][b] = c; hsum[0][b] = s;
    }
    __syncthreads();

    if (tid == 0) {
        int nneg = s_nneg, npos = s_npos;
        int k = (int)(RATIO * (float)nneg);
        float neg = 0.f; int cum = 0;
        for (int b = NB - 1; b >= 0 && cum < k; b--) {
            int c = hcnt[0][b];
            if (c == 0) continue;
            if (cum + c <= k) { neg += hsum[0][b]; cum += c; }
            else {
                int rem = k - cum;
                neg += hsum[0][b] * ((float)rem / (float)c);
                cum = k;
            }
        }
        float pos = s_pos / (float)max(npos, 1);
        bool valid = (k > 0) && (npos > 0);
        float denom = fmaxf(pos + neg, 1e-8f);
        float ratio = fminf(fmaxf(pos / denom, 1e-8f), 1.0f);
        float loss  = fminf(fmaxf(-logf(ratio), 0.f), 5.f);
        g_rowloss[r]  = valid ? loss : 0.f;
        g_rowvalid[r] = valid ? 1 : 0;
    }
}

// ---------------- K4: PRD (KL) per feature row ------------------------------
__global__ void __launch_bounds__(128) prd_kernel() {
    const int r = blockIdx.x;
    const int tid = threadIdx.x;
    __shared__ float fsh[D_];
    __shared__ float so[L_], sn[L_];
    for (int d = tid; d < D_; d += 128) fsh[d] = g_fnorm[r * D_ + d];
    __syncthreads();
    if (tid < 2 * L_) {
        const float* __restrict__ P = (tid < L_) ? (g_opn + tid * D_) : (g_npn + (tid - L_) * D_);
        float dot = 0.f;
        #pragma unroll 8
        for (int d = 0; d < D_; d++) dot = fmaf(fsh[d], P[d], dot);
        float s = fminf(fmaxf(dot * INV_TEMP, -10.f), 10.f);
        if (tid < L_) so[tid] = s; else sn[tid - L_] = s;
    }
    __syncthreads();
    if (tid == 0) {
        float maxo = -1e30f, maxn = -1e30f;
        for (int j = 0; j < L_; j++) { maxo = fmaxf(maxo, so[j]); maxn = fmaxf(maxn, sn[j]); }
        float sumo = 0.f, sumn = 0.f;
        for (int j = 0; j < L_; j++) { sumo += __expf(so[j] - maxo); sumn += __expf(sn[j] - maxn); }
        float lso = logf(sumo), lsn = logf(sumn);
        float kl = 0.f;
        for (int j = 0; j < L_; j++) {
            float lop = so[j] - maxo - lso;
            float lnp = sn[j] - maxn - lsn;
            kl += __expf(lop) * (lop - lnp);
        }
        atomicAdd(&g_kl[0], kl);
    }
}

// ---------------- K5: finalize ----------------------------------------------
__device__ __forceinline__ float block_reduce_256(float v, float* red) {
    int tid = threadIdx.x;
    red[tid] = v; __syncthreads();
    #pragma unroll
    for (int off = 128; off > 0; off >>= 1) {
        if (tid < off) red[tid] += red[tid + off];
        __syncthreads();
    }
    float r = red[0]; __syncthreads();
    return r;
}

__global__ void __launch_bounds__(256) finalize_kernel(float* __restrict__ out) {
    __shared__ float red[256];
    const int tid = threadIdx.x;
    float ls = 0.f, vs = 0.f;
    for (int r = tid; r < B_; r += 256) { ls += g_rowloss[r]; vs += (float)g_rowvalid[r]; }
    float ls_t = block_reduce_256(ls, red);
    float vs_t = block_reduce_256(vs, red);

    float blv = 0.f, bvc = 0.f;
    if (tid < C_) {
        float n = g_cnt[tid];
        float safen = fmaxf(n, 1.f);
        float vsum = 0.f;
        const float* sf = g_sumF + tid * D_;
        const float* sq = g_sumSq + tid * D_;
        for (int d = 0; d < D_; d++) {
            float mean = sf[d] / safen;
            float var  = (sq[d] - n * mean * mean) / fmaxf(n - 1.f, 1.f);
            vsum += var;
        }
        float var_mean = fminf(fmaxf(vsum / (float)D_, 1e-6f), 100.f);
        float target = 1.0f / (1.0f + __expf(-var_mean));
        float mean_s = g_sumS[tid] / safen;
        float diff = mean_s - target;
        float bl = fminf(fmaxf(diff * diff, 0.f), 2.f);
        if (n > 1.f) { blv = bl; bvc = 1.f; }
    }
    float bl_t  = block_reduce_256(blv, red);
    float bvc_t = block_reduce_256(bvc, red);

    if (tid == 0) {
        float hard = ls_t / fmaxf(vs_t, 1.f);
        float boundary = bl_t / fmaxf(bvc_t, 1.f);
        float prd = fminf(fmaxf(g_kl[0] / (float)B_, 0.f), 5.f);
        out[0] = hard + 0.1f * boundary + 0.2f * prd;
    }
}

// ---------------- launch ----------------------------------------------------
extern "C" void kernel_launch(void* const* d_in, const int* in_sizes, int n_in,
                              void* d_out, int out_size) {
    (void)in_sizes; (void)n_in; (void)out_size;
    const float* features = (const float*)d_in[0];
    const float* buffer   = (const float*)d_in[1];
    const float* protos   = (const float*)d_in[2];  // new prototypes
    const float* oldp     = (const float*)d_in[3];
    const float* W        = (const float*)d_in[4];
    const float* bb       = (const float*)d_in[5];
    const int*   labels   = (const int*)d_in[6];
    const int*   blabels  = (const int*)d_in[7];
    const int*   lc       = (const int*)d_in[8];
    float* out = (float*)d_out;

    zero_kernel<<<(C_ * D_ + 255) / 256, 256>>>();
    normalize_kernel<<<B_ + M_ + 2 * L_, 128>>>(features, buffer, oldp, protos, W, bb, labels, lc);
    gemm_sims_kernel<<<dim3(M_ / 128, B_ / 128), 256>>>();
    hard_kernel<<<B_, 256>>>(labels, blabels);
    prd_kernel<<<B_, 128>>>();
    finalize_kernel<<<1, 256>>>(out);
}

// round 3
// speedup vs baseline: 1.6575x; 1.6575x over previous
#include <cuda_runtime.h>
#include <cuda_bf16.h>
#include <math.h>
#include <stdint.h>

// ---------------- problem constants ----------------
#define B_   1024
#define M_   16384
#define D_   512
#define C_   100
#define L_   50
#define INV_TEMP 5.0f   // 1/0.2
#define RATIO 0.7f

// ---------------- device scratch (no allocations allowed) ----------------
__device__ float g_fnorm[B_ * D_];            // normalized features fp32 (PRD)
__device__ __nv_bfloat16 g_fb16[B_ * D_];     // normalized features bf16 (GEMM A)
__device__ __nv_bfloat16 g_bb16[M_ * D_];     // normalized buffer  bf16 (GEMM B)
__device__ float g_sims[(size_t)B_ * M_];     // similarity matrix (64 MB)
__device__ float g_opn[L_ * D_];
__device__ float g_npn[L_ * D_];
__device__ float g_cnt[C_];
__device__ float g_sumS[C_];
__device__ float g_sumF[C_ * D_];
__device__ float g_sumSq[C_ * D_];
__device__ float g_rowloss[B_];
__device__ int   g_rowvalid[B_];
__device__ float g_kl[1];

// ---------------- K0: zero accumulators ----------------
__global__ void zero_kernel() {
    int i = blockIdx.x * blockDim.x + threadIdx.x;
    if (i < C_ * D_) { g_sumF[i] = 0.f; g_sumSq[i] = 0.f; }
    if (i < C_)      { g_cnt[i] = 0.f; g_sumS[i] = 0.f; }
    if (i == 0)      { g_kl[0] = 0.f; }
}

// ---------------- K1: normalize rows (+ boundary stats + bf16 emit) --------
__global__ void __launch_bounds__(128) normalize_kernel(
    const float* __restrict__ features, const float* __restrict__ buffer,
    const float* __restrict__ oldp, const float* __restrict__ newp,
    const float* __restrict__ W, const float* __restrict__ bbias,
    const int* __restrict__ labels, const int* __restrict__ lc)
{
    const int blk = blockIdx.x;
    const int tid = threadIdx.x;
    const float* src; float* dst = nullptr; __nv_bfloat16* dst16 = nullptr;
    bool isFeat = false;
    if (blk < B_) { src = features + blk * D_; dst = g_fnorm + blk * D_; dst16 = g_fb16 + blk * D_; isFeat = true; }
    else if (blk < B_ + M_) { int r = blk - B_; src = buffer + (size_t)r * D_; dst16 = g_bb16 + (size_t)r * D_; }
    else if (blk < B_ + M_ + L_) { int j = blk - (B_ + M_); src = oldp + lc[j] * D_; dst = g_opn + j * D_; }
    else { int j = blk - (B_ + M_ + L_); src = newp + lc[j] * D_; dst = g_npn + j * D_; }

    float4 v = *(const float4*)(src + tid * 4);
    float ss = v.x*v.x + v.y*v.y + v.z*v.z + v.w*v.w;
    float wd = 0.f;
    if (isFeat) {
        float4 w4 = *(const float4*)(W + tid * 4);
        wd = v.x*w4.x + v.y*w4.y + v.z*w4.z + v.w*w4.w;
    }
    __shared__ float sh1[128], sh2[128];
    sh1[tid] = ss; sh2[tid] = wd; __syncthreads();
    #pragma unroll
    for (int off = 64; off > 0; off >>= 1) {
        if (tid < off) { sh1[tid] += sh1[tid + off]; sh2[tid] += sh2[tid + off]; }
        __syncthreads();
    }
    float inv = 1.0f / fmaxf(sqrtf(sh1[0]), 1e-12f);
    float4 o; o.x = v.x*inv; o.y = v.y*inv; o.z = v.z*inv; o.w = v.w*inv;
    if (dst) *(float4*)(dst + tid * 4) = o;
    if (dst16) {
        __nv_bfloat162 p0 = __floats2bfloat162_rn(o.x, o.y);
        __nv_bfloat162 p1 = __floats2bfloat162_rn(o.z, o.w);
        uint2 pk; pk.x = *(uint32_t*)&p0; pk.y = *(uint32_t*)&p1;
        *(uint2*)(dst16 + tid * 4) = pk;
    }

    if (isFeat) {
        int cl = labels[blk];
        if (tid == 0) {
            float score = 1.0f / (1.0f + __expf(-(sh2[0] + bbias[0])));
            atomicAdd(&g_cnt[cl], 1.0f);
            atomicAdd(&g_sumS[cl], score);
        }
        int base = cl * D_ + tid * 4;
        atomicAdd(&g_sumF[base + 0], v.x); atomicAdd(&g_sumSq[base + 0], v.x*v.x);
        atomicAdd(&g_sumF[base + 1], v.y); atomicAdd(&g_sumSq[base + 1], v.y*v.y);
        atomicAdd(&g_sumF[base + 2], v.z); atomicAdd(&g_sumSq[base + 2], v.z*v.z);
        atomicAdd(&g_sumF[base + 3], v.w); atomicAdd(&g_sumSq[base + 3], v.w*v.w);
    }
}

// ---------------- K2: bf16 tensor-core GEMM sims = A @ B^T * 5, clipped ----
// CTA tile 128x128, BK=32, 256 threads = 8 warps (4m x 2n), warp 32x64.
// mma.sync.m16n8k16 bf16->f32, cp.async double buffering.
#define LDT 40   // smem row stride in bf16 elems (32 data + 8 pad = 80B, 16B aligned)

__device__ __forceinline__ void cp_async16(void* smem, const void* gmem) {
    uint32_t s = (uint32_t)__cvta_generic_to_shared(smem);
    asm volatile("cp.async.cg.shared.global [%0], [%1], 16;\n" :: "r"(s), "l"(gmem));
}
__device__ __forceinline__ void ldsm_x4(uint32_t& r0, uint32_t& r1, uint32_t& r2, uint32_t& r3, const void* p) {
    uint32_t s = (uint32_t)__cvta_generic_to_shared(p);
    asm volatile("ldmatrix.sync.aligned.m8n8.x4.shared.b16 {%0,%1,%2,%3}, [%4];\n"
        : "=r"(r0), "=r"(r1), "=r"(r2), "=r"(r3) : "r"(s));
}
__device__ __forceinline__ void mma16816(float* c, uint32_t a0, uint32_t a1, uint32_t a2, uint32_t a3,
                                         uint32_t b0, uint32_t b1) {
    asm volatile("mma.sync.aligned.m16n8k16.row.col.f32.bf16.bf16.f32 "
        "{%0,%1,%2,%3},{%4,%5,%6,%7},{%8,%9},{%0,%1,%2,%3};\n"
        : "+f"(c[0]), "+f"(c[1]), "+f"(c[2]), "+f"(c[3])
        : "r"(a0), "r"(a1), "r"(a2), "r"(a3), "r"(b0), "r"(b1));
}

__global__ void __launch_bounds__(256) gemm_sims_kernel() {
    __shared__ __nv_bfloat16 sA[2][128 * LDT];
    __shared__ __nv_bfloat16 sB[2][128 * LDT];

    const int tid  = threadIdx.x;
    const int lane = tid & 31;
    const int wid  = tid >> 5;
    const int warp_m = wid & 3;       // 0..3  -> 32 rows each
    const int warp_n = wid >> 2;      // 0..1  -> 64 cols each
    const int rowBase = blockIdx.y * 128;
    const int colBase = blockIdx.x * 128;

    float acc[2][8][4];
    #pragma unroll
    for (int i = 0; i < 2; i++)
        #pragma unroll
        for (int j = 0; j < 8; j++)
            #pragma unroll
            for (int q = 0; q < 4; q++) acc[i][j][q] = 0.f;

    // load helper indices: 512 16B-chunks per operand, 2 per thread
    const int r0c = tid >> 2, c0c = tid & 3;                 // chunk set 0
    const int r1c = (tid + 256) >> 2, c1c = tid & 3;         // chunk set 1

    auto load_stage = [&](int buf, int kb) {
        const __nv_bfloat16* ga = g_fb16 + (size_t)(rowBase + r0c) * D_ + kb * 32 + c0c * 8;
        cp_async16(&sA[buf][r0c * LDT + c0c * 8], ga);
        const __nv_bfloat16* ga2 = g_fb16 + (size_t)(rowBase + r1c) * D_ + kb * 32 + c1c * 8;
        cp_async16(&sA[buf][r1c * LDT + c1c * 8], ga2);
        const __nv_bfloat16* gb = g_bb16 + (size_t)(colBase + r0c) * D_ + kb * 32 + c0c * 8;
        cp_async16(&sB[buf][r0c * LDT + c0c * 8], gb);
        const __nv_bfloat16* gb2 = g_bb16 + (size_t)(colBase + r1c) * D_ + kb * 32 + c1c * 8;
        cp_async16(&sB[buf][r1c * LDT + c1c * 8], gb2);
    };

    load_stage(0, 0);
    asm volatile("cp.async.commit_group;\n");

    const int NKB = D_ / 32;   // 16
    for (int kb = 0; kb < NKB; kb++) {
        int cur = kb & 1;
        if (kb + 1 < NKB) {
            load_stage(cur ^ 1, kb + 1);
            asm volatile("cp.async.commit_group;\n");
            asm volatile("cp.async.wait_group 1;\n");
        } else {
            asm volatile("cp.async.wait_group 0;\n");
        }
        __syncthreads();

        #pragma unroll
        for (int ks = 0; ks < 32; ks += 16) {
            uint32_t a[2][4], b[4][4];
            #pragma unroll
            for (int tm = 0; tm < 2; tm++) {
                int row = warp_m * 32 + tm * 16 + (lane & 15);
                int col = ks + (lane >> 4) * 8;
                ldsm_x4(a[tm][0], a[tm][1], a[tm][2], a[tm][3], &sA[cur][row * LDT + col]);
            }
            #pragma unroll
            for (int tp = 0; tp < 4; tp++) {
                int row = warp_n * 64 + tp * 16 + (lane & 15);
                int col = ks + (lane >> 4) * 8;
                ldsm_x4(b[tp][0], b[tp][1], b[tp][2], b[tp][3], &sB[cur][row * LDT + col]);
            }
            // ldsm on [n][k] tile: b[tp][0]=(n0-7,klo) b[tp][1]=(n8-15,klo)
            //                      b[tp][2]=(n0-7,khi) b[tp][3]=(n8-15,khi)
            // mma B operand for n-half hi needs {klo,khi} of SAME half: {b[hi], b[hi+2]}
            #pragma unroll
            for (int tm = 0; tm < 2; tm++)
                #pragma unroll
                for (int tn = 0; tn < 8; tn++) {
                    int tp = tn >> 1, hi = tn & 1;
                    mma16816(acc[tm][tn], a[tm][0], a[tm][1], a[tm][2], a[tm][3],
                             b[tp][hi], b[tp][hi + 2]);
                }
        }
        __syncthreads();
    }

    // epilogue: scale*5, clip +-10, fp32 store
    #pragma unroll
    for (int tm = 0; tm < 2; tm++) {
        int r0 = rowBase + warp_m * 32 + tm * 16 + (lane >> 2);
        #pragma unroll
        for (int tn = 0; tn < 8; tn++) {
            int c0 = colBase + warp_n * 64 + tn * 8 + (lane & 3) * 2;
            float2 lo, hi2;
            lo.x  = fminf(fmaxf(acc[tm][tn][0] * INV_TEMP, -10.f), 10.f);
            lo.y  = fminf(fmaxf(acc[tm][tn][1] * INV_TEMP, -10.f), 10.f);
            hi2.x = fminf(fmaxf(acc[tm][tn][2] * INV_TEMP, -10.f), 10.f);
            hi2.y = fminf(fmaxf(acc[tm][tn][3] * INV_TEMP, -10.f), 10.f);
            *(float2*)&g_sims[(size_t)r0 * M_ + c0] = lo;
            *(float2*)&g_sims[(size_t)(r0 + 8) * M_ + c0] = hi2;
        }
    }
}

// ---------------- K3: per-row hard-negative loss ---------------------------
// One block (256 threads) per row. Warp-private 512-bin histograms with a
// SINGLE packed 64-bit atomic per element: count in bits[63:44],
// exp-sum as 2^20 fixed point in bits[43:0].
#define NB 512
#define HSCALE 25.6f   // NB / 20
#define FIXSCALE 1048576.0f
__global__ void __launch_bounds__(256) hard_kernel(
    const int* __restrict__ labels, const int* __restrict__ blabels)
{
    const int r   = blockIdx.x;
    const int tid = threadIdx.x;
    const int wid = tid >> 5;
    __shared__ unsigned long long hist[8][NB];   // 32 KB
    __shared__ float s_pos; __shared__ int s_npos, s_nneg;

    for (int i = tid; i < 8 * NB; i += 256) ((unsigned long long*)hist)[i] = 0ull;
    if (tid == 0) { s_pos = 0.f; s_npos = 0; s_nneg = 0; }
    __syncthreads();

    const int lbl = labels[r];
    const float* __restrict__ row = g_sims + (size_t)r * M_;
    float lpos = 0.f; int lnp = 0, lnn = 0;
    for (int m = tid; m < M_; m += 256) {
        float s = row[m];
        float e = __expf(s);
        if (blabels[m] != lbl) {
            lnn++;
            int bin = (int)((s + 10.f) * HSCALE);
            bin = min(max(bin, 0), NB - 1);
            unsigned long long pk = (1ull << 44) | (unsigned long long)(e * FIXSCALE);
            atomicAdd(&hist[wid][bin], pk);
        } else { lpos += e; lnp++; }
    }
    atomicAdd(&s_pos, lpos); atomicAdd(&s_npos, lnp); atomicAdd(&s_nneg, lnn);
    __syncthreads();

    // reduce 8 warp copies into copy 0
    for (int b = tid; b < NB; b += 256) {
        unsigned long long v = hist[0][b];
        #pragma unroll
        for (int w = 1; w < 8; w++) v += hist[w][b];
        hist[0][b] = v;
    }
    __syncthreads();

    if (tid == 0) {
        int nneg = s_nneg, npos = s_npos;
        int k = (int)(RATIO * (float)nneg);
        float neg = 0.f; int cum = 0;
        const unsigned long long SMASK = (1ull << 44) - 1ull;
        for (int b = NB - 1; b >= 0 && cum < k; b--) {
            unsigned long long v = hist[0][b];
            int c = (int)(v >> 44);
            if (c == 0) continue;
            float s = (float)((double)(v & SMASK) * (1.0 / 1048576.0));
            if (cum + c <= k) { neg += s; cum += c; }
            else {
                int rem = k - cum;
                neg += s * ((float)rem / (float)c);
                cum = k;
            }
        }
        float pos = s_pos / (float)max(npos, 1);
        bool valid = (k > 0) && (npos > 0);
        float denom = fmaxf(pos + neg, 1e-8f);
        float ratio = fminf(fmaxf(pos / denom, 1e-8f), 1.0f);
        float loss  = fminf(fmaxf(-logf(ratio), 0.f), 5.f);
        g_rowloss[r]  = valid ? loss : 0.f;
        g_rowvalid[r] = valid ? 1 : 0;
    }
}

// ---------------- K4: PRD (KL) per feature row ------------------------------
__global__ void __launch_bounds__(128) prd_kernel() {
    const int r = blockIdx.x;
    const int tid = threadIdx.x;
    __shared__ float fsh[D_];
    __shared__ float so[L_], sn[L_];
    for (int d = tid; d < D_; d += 128) fsh[d] = g_fnorm[r * D_ + d];
    __syncthreads();
    if (tid < 2 * L_) {
        const float* __restrict__ P = (tid < L_) ? (g_opn + tid * D_) : (g_npn + (tid - L_) * D_);
        float dot = 0.f;
        #pragma unroll 8
        for (int d = 0; d < D_; d++) dot = fmaf(fsh[d], P[d], dot);
        float s = fminf(fmaxf(dot * INV_TEMP, -10.f), 10.f);
        if (tid < L_) so[tid] = s; else sn[tid - L_] = s;
    }
    __syncthreads();
    if (tid == 0) {
        float maxo = -1e30f, maxn = -1e30f;
        for (int j = 0; j < L_; j++) { maxo = fmaxf(maxo, so[j]); maxn = fmaxf(maxn, sn[j]); }
        float sumo = 0.f, sumn = 0.f;
        for (int j = 0; j < L_; j++) { sumo += __expf(so[j] - maxo); sumn += __expf(sn[j] - maxn); }
        float lso = logf(sumo), lsn = logf(sumn);
        float kl = 0.f;
        for (int j = 0; j < L_; j++) {
            float lop = so[j] - maxo - lso;
            float lnp = sn[j] - maxn - lsn;
            kl += __expf(lop) * (lop - lnp);
        }
        atomicAdd(&g_kl[0], kl);
    }
}

// ---------------- K5: finalize ----------------------------------------------
__device__ __forceinline__ float block_reduce_256(float v, float* red) {
    int tid = threadIdx.x;
    red[tid] = v; __syncthreads();
    #pragma unroll
    for (int off = 128; off > 0; off >>= 1) {
        if (tid < off) red[tid] += red[tid + off];
        __syncthreads();
    }
    float r = red[0]; __syncthreads();
    return r;
}

__global__ void __launch_bounds__(256) finalize_kernel(float* __restrict__ out) {
    __shared__ float red[256];
    const int tid = threadIdx.x;
    float ls = 0.f, vs = 0.f;
    for (int r = tid; r < B_; r += 256) { ls += g_rowloss[r]; vs += (float)g_rowvalid[r]; }
    float ls_t = block_reduce_256(ls, red);
    float vs_t = block_reduce_256(vs, red);

    float blv = 0.f, bvc = 0.f;
    if (tid < C_) {
        float n = g_cnt[tid];
        float safen = fmaxf(n, 1.f);
        float vsum = 0.f;
        const float* sf = g_sumF + tid * D_;
        const float* sq = g_sumSq + tid * D_;
        for (int d = 0; d < D_; d++) {
            float mean = sf[d] / safen;
            float var  = (sq[d] - n * mean * mean) / fmaxf(n - 1.f, 1.f);
            vsum += var;
        }
        float var_mean = fminf(fmaxf(vsum / (float)D_, 1e-6f), 100.f);
        float target = 1.0f / (1.0f + __expf(-var_mean));
        float mean_s = g_sumS[tid] / safen;
        float diff = mean_s - target;
        float bl = fminf(fmaxf(diff * diff, 0.f), 2.f);
        if (n > 1.f) { blv = bl; bvc = 1.f; }
    }
    float bl_t  = block_reduce_256(blv, red);
    float bvc_t = block_reduce_256(bvc, red);

    if (tid == 0) {
        float hard = ls_t / fmaxf(vs_t, 1.f);
        float boundary = bl_t / fmaxf(bvc_t, 1.f);
        float prd = fminf(fmaxf(g_kl[0] / (float)B_, 0.f), 5.f);
        out[0] = hard + 0.1f * boundary + 0.2f * prd;
    }
}

// ---------------- launch ----------------------------------------------------
extern "C" void kernel_launch(void* const* d_in, const int* in_sizes, int n_in,
                              void* d_out, int out_size) {
    (void)in_sizes; (void)n_in; (void)out_size;
    const float* features = (const float*)d_in[0];
    const float* buffer   = (const float*)d_in[1];
    const float* protos   = (const float*)d_in[2];  // new prototypes
    const float* oldp     = (const float*)d_in[3];
    const float* W        = (const float*)d_in[4];
    const float* bb       = (const float*)d_in[5];
    const int*   labels   = (const int*)d_in[6];
    const int*   blabels  = (const int*)d_in[7];
    const int*   lc       = (const int*)d_in[8];
    float* out = (float*)d_out;

    zero_kernel<<<(C_ * D_ + 255) / 256, 256>>>();
    normalize_kernel<<<B_ + M_ + 2 * L_, 128>>>(features, buffer, oldp, protos, W, bb, labels, lc);
    gemm_sims_kernel<<<dim3(M_ / 128, B_ / 128), 256>>>();
    hard_kernel<<<B_, 256>>>(labels, blabels);
    prd_kernel<<<B_, 128>>>();
    finalize_kernel<<<1, 256>>>(out);
}